// round 1
// baseline (speedup 1.0000x reference)
#include <cuda_runtime.h>
#include <cstdint>

#define MAXN 100000
#define MAXE 1600000
#define HD 128
#define SLOPE 0.2f

// ---------------- scratch (device globals; no runtime allocation) ----------------
__device__ float    g_xp1[(size_t)MAXN * HD];   // layer1 x@W1
__device__ float    g_out1[(size_t)MAXN * HD];  // layer1 aggregation / x1
__device__ float    g_es[MAXN];                 // e_src per node (layer1)
__device__ float    g_ed[MAXN];                 // e_dst per node (layer1)
__device__ unsigned g_menc[MAXN];               // segment max (monotone-encoded float)
__device__ float    g_denom[MAXN];              // softmax denominator
__device__ float    g_aself[MAXN];              // self-loop alpha
__device__ float    g_xp2[MAXN];                // layer2 x@W2 (OUT=1)
__device__ int      g_cs[MAXE];                 // compacted src
__device__ int      g_cd[MAXE];                 // compacted dst
__device__ float    g_ew[MAXE];                 // edge exp weights
__device__ int      g_cnt;                      // active edge count

// ---------------- helpers ----------------
__device__ __forceinline__ float lrelu(float x) { return x > 0.f ? x : SLOPE * x; }

// monotone float <-> uint encoding so atomicMax works for signed floats
__device__ __forceinline__ unsigned fenc(float f) {
    unsigned u = __float_as_uint(f);
    return (u & 0x80000000u) ? ~u : (u | 0x80000000u);
}
__device__ __forceinline__ float fdec(unsigned u) {
    return (u & 0x80000000u) ? __uint_as_float(u & 0x7fffffffu) : __uint_as_float(~u);
}

__device__ __forceinline__ void red_add_v4(float* p, float a, float b, float c, float d) {
    asm volatile("red.global.add.v4.f32 [%0], {%1,%2,%3,%4};"
                 :: "l"(p), "f"(a), "f"(b), "f"(c), "f"(d) : "memory");
}

// ---------------- kernels ----------------
__global__ void k_reset() {
    if (threadIdx.x == 0 && blockIdx.x == 0) g_cnt = 0;
}

// compact active edges (both endpoints type 0); warp-aggregated atomics
__global__ void k_compact(const int* __restrict__ ei, const int* __restrict__ nt, int E) {
    int Er = (E + 31) & ~31;
    int lane = threadIdx.x & 31;
    int stride = gridDim.x * blockDim.x;
    for (int i = blockIdx.x * blockDim.x + threadIdx.x; i < Er; i += stride) {
        int s = 0, d = 0;
        bool act = false;
        if (i < E) {
            s = ei[i];
            d = ei[E + i];
            act = (nt[s] == 0) && (nt[d] == 0);
        }
        unsigned ball = __ballot_sync(0xffffffffu, act);
        if (ball) {
            int leader = __ffs(ball) - 1;
            int base = 0;
            if (lane == leader) base = atomicAdd(&g_cnt, __popc(ball));
            base = __shfl_sync(0xffffffffu, base, leader);
            if (act) {
                int off = __popc(ball & ((1u << lane) - 1u));
                g_cs[base + off] = s;
                g_cd[base + off] = d;
            }
        }
    }
}

// GEMM1: xp1 = emb[h] @ W1, fused e_src/e_dst epilogue.
// Block: 256 threads, 64 rows x 128 cols, K staged in 32-chunks through smem.
__global__ void __launch_bounds__(256) k_gemm1(
    const int* __restrict__ hidx, const float* __restrict__ emb,
    const float* __restrict__ W,
    const float* __restrict__ as1, const float* __restrict__ ad1, int N)
{
    __shared__ float xs[32][64];    // [k][m] transposed x tile
    __shared__ float ws[32][128];   // [k][n] W tile

    int tid = threadIdx.x;
    int tx = tid & 31;      // col group (lane)
    int ty = tid >> 5;      // row group (warp)
    int c0 = tx * 4;
    int r0 = ty * 8;
    int m0 = blockIdx.x * 64;

    float acc[8][4];
#pragma unroll
    for (int r = 0; r < 8; r++)
#pragma unroll
        for (int c = 0; c < 4; c++) acc[r][c] = 0.f;

    // this thread's tile row for x loads (same m for j=0,1 and all k-tiles)
    int idx0 = tid * 2;
    int mA = idx0 >> 3;
    int rowA = m0 + mA;
    bool okA = rowA < N;
    int hA = okA ? hidx[rowA] : 0;

    for (int kt = 0; kt < HD; kt += 32) {
#pragma unroll
        for (int j = 0; j < 2; j++) {
            int idx = idx0 + j;
            int kq = idx & 7;
            float4 v = make_float4(0.f, 0.f, 0.f, 0.f);
            if (okA) v = *(const float4*)&emb[(size_t)hA * HD + kt + kq * 4];
            xs[kq * 4 + 0][mA] = v.x;
            xs[kq * 4 + 1][mA] = v.y;
            xs[kq * 4 + 2][mA] = v.z;
            xs[kq * 4 + 3][mA] = v.w;
        }
#pragma unroll
        for (int t = 0; t < 4; t++) {
            int idx = tid + t * 256;
            int kk = idx >> 5, nq = idx & 31;
            *(float4*)&ws[kk][nq * 4] = *(const float4*)&W[(size_t)(kt + kk) * HD + nq * 4];
        }
        __syncthreads();

#pragma unroll 8
        for (int kk = 0; kk < 32; kk++) {
            float4 xa = *(float4*)&xs[kk][r0];
            float4 xb = *(float4*)&xs[kk][r0 + 4];
            float4 wq = *(float4*)&ws[kk][c0];
            float xv[8] = {xa.x, xa.y, xa.z, xa.w, xb.x, xb.y, xb.z, xb.w};
            float wv[4] = {wq.x, wq.y, wq.z, wq.w};
#pragma unroll
            for (int r = 0; r < 8; r++)
#pragma unroll
                for (int c = 0; c < 4; c++)
                    acc[r][c] += xv[r] * wv[c];
        }
        __syncthreads();
    }

    float4 av = *(const float4*)&as1[c0];
    float4 dv = *(const float4*)&ad1[c0];
#pragma unroll
    for (int r = 0; r < 8; r++) {
        int row = m0 + r0 + r;
        bool ok = row < N;
        if (ok) {
            *(float4*)&g_xp1[(size_t)row * HD + c0] =
                make_float4(acc[r][0], acc[r][1], acc[r][2], acc[r][3]);
        }
        float ps = acc[r][0] * av.x + acc[r][1] * av.y + acc[r][2] * av.z + acc[r][3] * av.w;
        float pd = acc[r][0] * dv.x + acc[r][1] * dv.y + acc[r][2] * dv.z + acc[r][3] * dv.w;
#pragma unroll
        for (int off = 16; off; off >>= 1) {
            ps += __shfl_xor_sync(0xffffffffu, ps, off);
            pd += __shfl_xor_sync(0xffffffffu, pd, off);
        }
        if (tx == 0 && ok) {
            g_es[row] = ps;
            g_ed[row] = pd;
        }
    }
}

// ---- layer 1 softmax passes ----
__global__ void k_init1(int N) {
    int i = blockIdx.x * blockDim.x + threadIdx.x;
    if (i < N) {
        float self = lrelu(g_es[i] + g_ed[i]);
        g_menc[i] = fenc(self);
    }
}

__global__ void k_max1() {
    int cnt = g_cnt;
    int st = gridDim.x * blockDim.x;
    for (int i = blockIdx.x * blockDim.x + threadIdx.x; i < cnt; i += st) {
        int s = g_cs[i], d = g_cd[i];
        float l = lrelu(g_es[s] + g_ed[d]);
        atomicMax(&g_menc[d], fenc(l));
    }
}

__global__ void k_denominit1(int N) {
    int i = blockIdx.x * blockDim.x + threadIdx.x;
    if (i < N) {
        float m = fdec(g_menc[i]);
        float self = lrelu(g_es[i] + g_ed[i]);
        g_denom[i] = __expf(self - m);
    }
}

__global__ void k_edgedenom1() {
    int cnt = g_cnt;
    int st = gridDim.x * blockDim.x;
    for (int i = blockIdx.x * blockDim.x + threadIdx.x; i < cnt; i += st) {
        int s = g_cs[i], d = g_cd[i];
        float l = lrelu(g_es[s] + g_ed[d]);
        float w = __expf(l - fdec(g_menc[d]));
        g_ew[i] = w;
        atomicAdd(&g_denom[d], w);
    }
}

__global__ void k_aself1(int N) {
    int i = blockIdx.x * blockDim.x + threadIdx.x;
    if (i < N) {
        float m = fdec(g_menc[i]);
        float self = lrelu(g_es[i] + g_ed[i]);
        g_aself[i] = __expf(self - m) / g_denom[i];
    }
}

// out1 = aself * xp1 (vectorized, float4 granularity)
__global__ void k_scale1(int N) {
    int idx = blockIdx.x * blockDim.x + threadIdx.x;  // over N*32 float4s
    if (idx < N * 32) {
        int node = idx >> 5;
        float a = g_aself[node];
        float4 v = ((const float4*)g_xp1)[idx];
        ((float4*)g_out1)[idx] = make_float4(a * v.x, a * v.y, a * v.z, a * v.w);
    }
}

// out1[dst] += alpha * xp1[src]   (warp per edge, vectorized red)
__global__ void k_agg1() {
    int cnt = g_cnt;
    int lane = threadIdx.x & 31;
    int w = (blockIdx.x * blockDim.x + threadIdx.x) >> 5;
    int nw = (gridDim.x * blockDim.x) >> 5;
    for (int e = w; e < cnt; e += nw) {
        int s = g_cs[e], d = g_cd[e];
        float alpha = g_ew[e] / g_denom[d];
        float4 v = ((const float4*)&g_xp1[(size_t)s * HD])[lane];
        red_add_v4(&g_out1[(size_t)d * HD + lane * 4],
                   alpha * v.x, alpha * v.y, alpha * v.z, alpha * v.w);
    }
}

// xp2[i] = sum_k relu(out1[i][k] + b1[k]) * W2[k]   (warp per node; fuses bias+relu)
__global__ void k_gemm2(const float* __restrict__ b1, const float* __restrict__ W2, int N) {
    int lane = threadIdx.x & 31;
    int node = blockIdx.x * 8 + (threadIdx.x >> 5);
    if (node >= N) return;
    float4 o = *(const float4*)&g_out1[(size_t)node * HD + lane * 4];
    float4 b = *(const float4*)&b1[lane * 4];
    float4 w = *(const float4*)&W2[lane * 4];
    float s = fmaxf(o.x + b.x, 0.f) * w.x + fmaxf(o.y + b.y, 0.f) * w.y +
              fmaxf(o.z + b.z, 0.f) * w.z + fmaxf(o.w + b.w, 0.f) * w.w;
#pragma unroll
    for (int off = 16; off; off >>= 1) s += __shfl_xor_sync(0xffffffffu, s, off);
    if (lane == 0) g_xp2[node] = s;
}

// ---- layer 2 softmax passes (OUT = 1, scalar features) ----
__global__ void k_init2(const float* __restrict__ as2, const float* __restrict__ ad2, int N) {
    int i = blockIdx.x * blockDim.x + threadIdx.x;
    if (i < N) {
        float self = lrelu(g_xp2[i] * (as2[0] + ad2[0]));
        g_menc[i] = fenc(self);
    }
}

__global__ void k_max2(const float* __restrict__ as2, const float* __restrict__ ad2) {
    int cnt = g_cnt;
    float a = as2[0], b = ad2[0];
    int st = gridDim.x * blockDim.x;
    for (int i = blockIdx.x * blockDim.x + threadIdx.x; i < cnt; i += st) {
        int s = g_cs[i], d = g_cd[i];
        float l = lrelu(g_xp2[s] * a + g_xp2[d] * b);
        atomicMax(&g_menc[d], fenc(l));
    }
}

__global__ void k_denominit2(const float* __restrict__ as2, const float* __restrict__ ad2, int N) {
    int i = blockIdx.x * blockDim.x + threadIdx.x;
    if (i < N) {
        float m = fdec(g_menc[i]);
        float self = lrelu(g_xp2[i] * (as2[0] + ad2[0]));
        g_denom[i] = __expf(self - m);
    }
}

__global__ void k_edgedenom2(const float* __restrict__ as2, const float* __restrict__ ad2) {
    int cnt = g_cnt;
    float a = as2[0], b = ad2[0];
    int st = gridDim.x * blockDim.x;
    for (int i = blockIdx.x * blockDim.x + threadIdx.x; i < cnt; i += st) {
        int s = g_cs[i], d = g_cd[i];
        float l = lrelu(g_xp2[s] * a + g_xp2[d] * b);
        float w = __expf(l - fdec(g_menc[d]));
        g_ew[i] = w;
        atomicAdd(&g_denom[d], w);
    }
}

__global__ void k_out2init(const float* __restrict__ as2, const float* __restrict__ ad2,
                           const float* __restrict__ b2, float* __restrict__ out, int N) {
    int i = blockIdx.x * blockDim.x + threadIdx.x;
    if (i < N) {
        float m = fdec(g_menc[i]);
        float self = lrelu(g_xp2[i] * (as2[0] + ad2[0]));
        float aself = __expf(self - m) / g_denom[i];
        out[i] = aself * g_xp2[i] + b2[0];
    }
}

__global__ void k_agg2(float* __restrict__ out) {
    int cnt = g_cnt;
    int st = gridDim.x * blockDim.x;
    for (int i = blockIdx.x * blockDim.x + threadIdx.x; i < cnt; i += st) {
        int s = g_cs[i], d = g_cd[i];
        atomicAdd(&out[d], (g_ew[i] / g_denom[d]) * g_xp2[s]);
    }
}

// ---------------- launch ----------------
extern "C" void kernel_launch(void* const* d_in, const int* in_sizes, int n_in,
                              void* d_out, int out_size) {
    const int*   h    = (const int*)d_in[0];
    const int*   ei   = (const int*)d_in[1];
    const int*   nt   = (const int*)d_in[2];
    const float* emb  = (const float*)d_in[3];
    const float* W1   = (const float*)d_in[4];
    const float* as1  = (const float*)d_in[5];
    const float* ad1  = (const float*)d_in[6];
    const float* b1   = (const float*)d_in[7];
    const float* W2   = (const float*)d_in[8];
    const float* as2  = (const float*)d_in[9];
    const float* ad2  = (const float*)d_in[10];
    const float* b2   = (const float*)d_in[11];
    float* out = (float*)d_out;

    int N = in_sizes[0];
    int E = in_sizes[1] / 2;
    int nb = (N + 255) / 256;

    k_reset<<<1, 32>>>();
    k_compact<<<1024, 256>>>(ei, nt, E);

    // layer 1
    k_gemm1<<<(N + 63) / 64, 256>>>(h, emb, W1, as1, ad1, N);
    k_init1<<<nb, 256>>>(N);
    k_max1<<<1024, 256>>>();
    k_denominit1<<<nb, 256>>>(N);
    k_edgedenom1<<<1024, 256>>>();
    k_aself1<<<nb, 256>>>(N);
    k_scale1<<<(N * 32 + 255) / 256, 256>>>(N);
    k_agg1<<<1024, 256>>>();

    // layer 2
    k_gemm2<<<(N + 7) / 8, 256>>>(b1, W2, N);
    k_init2<<<nb, 256>>>(as2, ad2, N);
    k_max2<<<1024, 256>>>(as2, ad2);
    k_denominit2<<<nb, 256>>>(as2, ad2, N);
    k_edgedenom2<<<1024, 256>>>(as2, ad2);
    k_out2init<<<nb, 256>>>(as2, ad2, b2, out, N);
    k_agg2<<<1024, 256>>>(out);
}

// round 3
// speedup vs baseline: 1.0541x; 1.0541x over previous
#include <cuda_runtime.h>
#include <cstdint>

#define MAXN 100000
#define MAXE 1600000
#define HD 128
#define SLOPE 0.2f

// ---------------- scratch (device globals; no runtime allocation) ----------------
__device__ float    g_xp1[(size_t)MAXN * HD];   // layer1 x@W1
__device__ float    g_out1[(size_t)MAXN * HD];  // layer1 aggregation / x1
__device__ float    g_es[MAXN];                 // e_src per node (layer1)
__device__ float    g_ed[MAXN];                 // e_dst per node (layer1)
__device__ unsigned g_menc[MAXN];               // segment max (monotone-encoded float)
__device__ float    g_denom[MAXN];              // softmax denominator
__device__ float    g_xp2[MAXN];                // layer2 x@W2 (OUT=1)
__device__ int      g_cs[MAXE];                 // compacted src
__device__ int      g_cd[MAXE];                 // compacted dst
__device__ float    g_ew[MAXE];                 // edge exp weights
__device__ int      g_cnt;                      // active edge count

// ---------------- helpers ----------------
__device__ __forceinline__ float lrelu(float x) { return x > 0.f ? x : SLOPE * x; }

__device__ __forceinline__ unsigned fenc(float f) {
    unsigned u = __float_as_uint(f);
    return (u & 0x80000000u) ? ~u : (u | 0x80000000u);
}
__device__ __forceinline__ float fdec(unsigned u) {
    return (u & 0x80000000u) ? __uint_as_float(u & 0x7fffffffu) : __uint_as_float(~u);
}

__device__ __forceinline__ void red_add_v4(float* p, float a, float b, float c, float d) {
    asm volatile("red.global.add.v4.f32 [%0], {%1,%2,%3,%4};"
                 :: "l"(p), "f"(a), "f"(b), "f"(c), "f"(d) : "memory");
}

__device__ __forceinline__ uint32_t f2tf32(float f) {
    uint32_t r; asm("cvt.rna.tf32.f32 %0, %1;" : "=r"(r) : "f"(f)); return r;
}

// warp-level tensor-core mma: D[16x8] += A[16x8] * B[8x8], tf32 in, f32 accum
__device__ __forceinline__ void mma_tf32(float* c, const uint32_t* a, const uint32_t* b) {
    asm volatile("mma.sync.aligned.m16n8k8.row.col.f32.tf32.tf32.f32 "
                 "{%0,%1,%2,%3}, {%4,%5,%6,%7}, {%8,%9}, {%0,%1,%2,%3};"
                 : "+f"(c[0]), "+f"(c[1]), "+f"(c[2]), "+f"(c[3])
                 : "r"(a[0]), "r"(a[1]), "r"(a[2]), "r"(a[3]), "r"(b[0]), "r"(b[1]));
}

// ---------------- kernels ----------------
__global__ void k_reset() {
    if (threadIdx.x == 0 && blockIdx.x == 0) g_cnt = 0;
}

__global__ void k_compact(const int* __restrict__ ei, const int* __restrict__ nt, int E) {
    int Er = (E + 31) & ~31;
    int lane = threadIdx.x & 31;
    int stride = gridDim.x * blockDim.x;
    for (int i = blockIdx.x * blockDim.x + threadIdx.x; i < Er; i += stride) {
        int s = 0, d = 0;
        bool act = false;
        if (i < E) {
            s = ei[i];
            d = ei[E + i];
            act = (__ldg(&nt[s]) == 0) && (__ldg(&nt[d]) == 0);
        }
        unsigned ball = __ballot_sync(0xffffffffu, act);
        if (ball) {
            int leader = __ffs(ball) - 1;
            int base = 0;
            if (lane == leader) base = atomicAdd(&g_cnt, __popc(ball));
            base = __shfl_sync(0xffffffffu, base, leader);
            if (act) {
                int off = __popc(ball & ((1u << lane) - 1u));
                g_cs[base + off] = s;
                g_cd[base + off] = d;
            }
        }
    }
}

// =======================================================================
// GEMM1: xp1 = emb[h] @ W1 via mma.sync tf32 (m16n8k8).
// CTA: 256 thr, 128(M)x128(N) tile, K=128 in 4 smem-staged chunks of 32.
// smem A: [k][m] 136-pad (conflict-free frag loads); B: [k][n] 136-pad.
// Epilogue staged through smem: coalesced xp1 stores + fused e_src/e_dst
// dots + self-logit menc init.
// =======================================================================
static constexpr int KPAD = 136;
static constexpr int OPAD = 132;
static constexpr int SM_TOT = 128 * OPAD * 4;  // 67584 B (>= 2*32*KPAD*4 = 34816)

__global__ void __launch_bounds__(256, 1)
k_gemm1_tc(const int* __restrict__ hidx, const float* __restrict__ emb,
           const float* __restrict__ W,
           const float* __restrict__ as1, const float* __restrict__ ad1, int N)
{
    extern __shared__ char smem[];
    uint32_t* xs = (uint32_t*)smem;                      // [32][KPAD]
    uint32_t* ws = (uint32_t*)(smem + 32 * KPAD * 4);    // [32][KPAD]
    float*    os = (float*)smem;                         // [128][OPAD] (epilogue reuse)

    int tid  = threadIdx.x;
    int lane = tid & 31;
    int wid  = tid >> 5;
    int g    = lane >> 2;   // groupID
    int tg   = lane & 3;    // thread-in-group
    int m_base = (wid & 3) * 32;
    int n_base = (wid >> 2) * 64;
    int blk0 = blockIdx.x * 128;

    float acc[2][8][4];
#pragma unroll
    for (int mf = 0; mf < 2; mf++)
#pragma unroll
        for (int nf = 0; nf < 8; nf++)
#pragma unroll
            for (int q = 0; q < 4; q++) acc[mf][nf][q] = 0.f;

    // A-gather mapping: thread -> (row = tid/2, half = tid&1) covers 16 k's/chunk
    int arow = tid >> 1;
    int ahalf = tid & 1;
    int grow = blk0 + arow;
    int hrow = (grow < N) ? __ldg(&hidx[grow]) : 0;
    const float4* aptr = (const float4*)&emb[(size_t)hrow * HD];

    // B mapping: thread -> (kk = tid/8, seg = tid&7) covers 16 n's/chunk
    int bkk = tid >> 3;
    int bseg = tid & 7;

    for (int kc = 0; kc < 4; kc++) {
        // ---- stage A chunk (transpose to [k][m], cvt tf32) ----
#pragma unroll
        for (int q = 0; q < 4; q++) {
            float4 v = __ldg(&aptr[kc * 8 + ahalf * 4 + q]);
            int k = ahalf * 16 + q * 4;
            xs[(k + 0) * KPAD + arow] = f2tf32(v.x);
            xs[(k + 1) * KPAD + arow] = f2tf32(v.y);
            xs[(k + 2) * KPAD + arow] = f2tf32(v.z);
            xs[(k + 3) * KPAD + arow] = f2tf32(v.w);
        }
        // ---- stage B chunk ([k][n], cvt tf32) ----
        {
            const float4* bptr = (const float4*)&W[(size_t)(kc * 32 + bkk) * HD + bseg * 16];
#pragma unroll
            for (int q = 0; q < 4; q++) {
                float4 v = __ldg(&bptr[q]);
                uint4 u = make_uint4(f2tf32(v.x), f2tf32(v.y), f2tf32(v.z), f2tf32(v.w));
                *(uint4*)&ws[bkk * KPAD + bseg * 16 + q * 4] = u;
            }
        }
        __syncthreads();

#pragma unroll
        for (int ks = 0; ks < 4; ks++) {
            int k0 = ks * 8;
            uint32_t af[2][4], bf[8][2];
#pragma unroll
            for (int mf = 0; mf < 2; mf++) {
                int m0 = m_base + mf * 16;
                af[mf][0] = xs[(k0 + tg) * KPAD + m0 + g];
                af[mf][1] = xs[(k0 + tg) * KPAD + m0 + g + 8];
                af[mf][2] = xs[(k0 + tg + 4) * KPAD + m0 + g];
                af[mf][3] = xs[(k0 + tg + 4) * KPAD + m0 + g + 8];
            }
#pragma unroll
            for (int nf = 0; nf < 8; nf++) {
                int n0 = n_base + nf * 8;
                bf[nf][0] = ws[(k0 + tg) * KPAD + n0 + g];
                bf[nf][1] = ws[(k0 + tg + 4) * KPAD + n0 + g];
            }
#pragma unroll
            for (int mf = 0; mf < 2; mf++)
#pragma unroll
                for (int nf = 0; nf < 8; nf++)
                    mma_tf32(acc[mf][nf], af[mf], bf[nf]);
        }
        __syncthreads();
    }

    // ---- stage D into smem for coalesced output ----
#pragma unroll
    for (int mf = 0; mf < 2; mf++) {
        int r0 = m_base + mf * 16 + g;
#pragma unroll
        for (int nf = 0; nf < 8; nf++) {
            int c0 = n_base + nf * 8 + tg * 2;
            os[r0 * OPAD + c0]       = acc[mf][nf][0];
            os[r0 * OPAD + c0 + 1]   = acc[mf][nf][1];
            os[(r0 + 8) * OPAD + c0]     = acc[mf][nf][2];
            os[(r0 + 8) * OPAD + c0 + 1] = acc[mf][nf][3];
        }
    }
    __syncthreads();

    // ---- output: each warp handles 16 rows; fused e_src/e_dst + menc init ----
    float4 av = __ldg((const float4*)&as1[lane * 4]);
    float4 dv = __ldg((const float4*)&ad1[lane * 4]);
#pragma unroll
    for (int rr = 0; rr < 16; rr++) {
        int r = wid * 16 + rr;
        int row = blk0 + r;
        float4 v = *(const float4*)&os[r * OPAD + lane * 4];
        float ps = v.x * av.x + v.y * av.y + v.z * av.z + v.w * av.w;
        float pd = v.x * dv.x + v.y * dv.y + v.z * dv.z + v.w * dv.w;
#pragma unroll
        for (int off = 16; off; off >>= 1) {
            ps += __shfl_xor_sync(0xffffffffu, ps, off);
            pd += __shfl_xor_sync(0xffffffffu, pd, off);
        }
        if (row < N) {
            *(float4*)&g_xp1[(size_t)row * HD + lane * 4] = v;
            if (lane == 0) {
                g_es[row] = ps;
                g_ed[row] = pd;
                g_menc[row] = fenc(lrelu(ps + pd));
            }
        }
    }
}

// ---- layer 1 softmax passes ----
__global__ void k_max1() {
    int cnt = g_cnt;
    int st = gridDim.x * blockDim.x;
    for (int i = blockIdx.x * blockDim.x + threadIdx.x; i < cnt; i += st) {
        int s = g_cs[i], d = g_cd[i];
        float l = lrelu(__ldg(&g_es[s]) + __ldg(&g_ed[d]));
        atomicMax(&g_menc[d], fenc(l));
    }
}

__global__ void k_denominit1(int N) {
    int i = blockIdx.x * blockDim.x + threadIdx.x;
    if (i < N) {
        float m = fdec(g_menc[i]);
        float self = lrelu(g_es[i] + g_ed[i]);
        g_denom[i] = __expf(self - m);
    }
}

__global__ void k_edgedenom1() {
    int cnt = g_cnt;
    int st = gridDim.x * blockDim.x;
    for (int i = blockIdx.x * blockDim.x + threadIdx.x; i < cnt; i += st) {
        int s = g_cs[i], d = g_cd[i];
        float l = lrelu(__ldg(&g_es[s]) + __ldg(&g_ed[d]));
        float w = __expf(l - fdec(g_menc[d]));
        g_ew[i] = w;
        atomicAdd(&g_denom[d], w);
    }
}

// out1 = alpha_self * xp1  (aself computed inline; float4 granularity)
__global__ void k_scale1(int N) {
    int idx = blockIdx.x * blockDim.x + threadIdx.x;  // over N*32 float4s
    if (idx < N * 32) {
        int node = idx >> 5;
        float m = fdec(__ldg(&g_menc[node]));
        float self = lrelu(__ldg(&g_es[node]) + __ldg(&g_ed[node]));
        float a = __expf(self - m) * __frcp_rn(__ldg(&g_denom[node]));
        float4 v = ((const float4*)g_xp1)[idx];
        ((float4*)g_out1)[idx] = make_float4(a * v.x, a * v.y, a * v.z, a * v.w);
    }
}

// out1[dst] += alpha * xp1[src]   (warp per edge, vectorized red)
__global__ void k_agg1() {
    int cnt = g_cnt;
    int lane = threadIdx.x & 31;
    int w = (blockIdx.x * blockDim.x + threadIdx.x) >> 5;
    int nw = (gridDim.x * blockDim.x) >> 5;
    for (int e = w; e < cnt; e += nw) {
        int s = g_cs[e], d = g_cd[e];
        float alpha = g_ew[e] / __ldg(&g_denom[d]);
        float4 v = __ldg(((const float4*)&g_xp1[(size_t)s * HD]) + lane);
        red_add_v4(&g_out1[(size_t)d * HD + lane * 4],
                   alpha * v.x, alpha * v.y, alpha * v.z, alpha * v.w);
    }
}

// xp2[i] = sum_k relu(out1[i][k]+b1[k])*W2[k]; fused layer-2 self-logit init
__global__ void k_gemm2(const float* __restrict__ b1, const float* __restrict__ W2,
                        const float* __restrict__ as2, const float* __restrict__ ad2, int N) {
    int lane = threadIdx.x & 31;
    int node = blockIdx.x * 8 + (threadIdx.x >> 5);
    if (node >= N) return;
    float4 o = *(const float4*)&g_out1[(size_t)node * HD + lane * 4];
    float4 b = __ldg((const float4*)&b1[lane * 4]);
    float4 w = __ldg((const float4*)&W2[lane * 4]);
    float s = fmaxf(o.x + b.x, 0.f) * w.x + fmaxf(o.y + b.y, 0.f) * w.y +
              fmaxf(o.z + b.z, 0.f) * w.z + fmaxf(o.w + b.w, 0.f) * w.w;
#pragma unroll
    for (int off = 16; off; off >>= 1) s += __shfl_xor_sync(0xffffffffu, s, off);
    if (lane == 0) {
        g_xp2[node] = s;
        g_menc[node] = fenc(lrelu(s * (__ldg(&as2[0]) + __ldg(&ad2[0]))));
    }
}

// ---- layer 2 softmax passes (OUT = 1) ----
__global__ void k_max2(const float* __restrict__ as2, const float* __restrict__ ad2) {
    int cnt = g_cnt;
    float a = __ldg(&as2[0]), b = __ldg(&ad2[0]);
    int st = gridDim.x * blockDim.x;
    for (int i = blockIdx.x * blockDim.x + threadIdx.x; i < cnt; i += st) {
        int s = g_cs[i], d = g_cd[i];
        float l = lrelu(__ldg(&g_xp2[s]) * a + __ldg(&g_xp2[d]) * b);
        atomicMax(&g_menc[d], fenc(l));
    }
}

__global__ void k_denominit2(const float* __restrict__ as2, const float* __restrict__ ad2, int N) {
    int i = blockIdx.x * blockDim.x + threadIdx.x;
    if (i < N) {
        float m = fdec(g_menc[i]);
        float self = lrelu(g_xp2[i] * (__ldg(&as2[0]) + __ldg(&ad2[0])));
        g_denom[i] = __expf(self - m);
    }
}

__global__ void k_edgedenom2(const float* __restrict__ as2, const float* __restrict__ ad2) {
    int cnt = g_cnt;
    float a = __ldg(&as2[0]), b = __ldg(&ad2[0]);
    int st = gridDim.x * blockDim.x;
    for (int i = blockIdx.x * blockDim.x + threadIdx.x; i < cnt; i += st) {
        int s = g_cs[i], d = g_cd[i];
        float l = lrelu(__ldg(&g_xp2[s]) * a + __ldg(&g_xp2[d]) * b);
        float w = __expf(l - fdec(g_menc[d]));
        g_ew[i] = w;
        atomicAdd(&g_denom[d], w);
    }
}

__global__ void k_out2init(const float* __restrict__ as2, const float* __restrict__ ad2,
                           const float* __restrict__ b2, float* __restrict__ out, int N) {
    int i = blockIdx.x * blockDim.x + threadIdx.x;
    if (i < N) {
        float m = fdec(g_menc[i]);
        float self = lrelu(g_xp2[i] * (__ldg(&as2[0]) + __ldg(&ad2[0])));
        float aself = __expf(self - m) / g_denom[i];
        out[i] = aself * g_xp2[i] + __ldg(&b2[0]);
    }
}

__global__ void k_agg2(float* __restrict__ out) {
    int cnt = g_cnt;
    int st = gridDim.x * blockDim.x;
    for (int i = blockIdx.x * blockDim.x + threadIdx.x; i < cnt; i += st) {
        int s = g_cs[i], d = g_cd[i];
        atomicAdd(&out[d], (g_ew[i] / __ldg(&g_denom[d])) * __ldg(&g_xp2[s]));
    }
}

// ---------------- launch ----------------
extern "C" void kernel_launch(void* const* d_in, const int* in_sizes, int n_in,
                              void* d_out, int out_size) {
    const int*   h    = (const int*)d_in[0];
    const int*   ei   = (const int*)d_in[1];
    const int*   nt   = (const int*)d_in[2];
    const float* emb  = (const float*)d_in[3];
    const float* W1   = (const float*)d_in[4];
    const float* as1  = (const float*)d_in[5];
    const float* ad1  = (const float*)d_in[6];
    const float* b1   = (const float*)d_in[7];
    const float* W2   = (const float*)d_in[8];
    const float* as2  = (const float*)d_in[9];
    const float* ad2  = (const float*)d_in[10];
    const float* b2   = (const float*)d_in[11];
    float* out = (float*)d_out;

    int N = in_sizes[0];
    int E = in_sizes[1] / 2;
    int nb = (N + 255) / 256;

    static bool attr_set = false;
    if (!attr_set) {
        cudaFuncSetAttribute(k_gemm1_tc, cudaFuncAttributeMaxDynamicSharedMemorySize, SM_TOT);
        attr_set = true;
    }

    k_reset<<<1, 32>>>();
    k_compact<<<1024, 256>>>(ei, nt, E);

    // layer 1
    k_gemm1_tc<<<(N + 127) / 128, 256, SM_TOT>>>(h, emb, W1, as1, ad1, N);
    k_max1<<<1024, 256>>>();
    k_denominit1<<<nb, 256>>>(N);
    k_edgedenom1<<<1024, 256>>>();
    k_scale1<<<(N * 32 + 255) / 256, 256>>>(N);
    k_agg1<<<1024, 256>>>();

    // layer 2
    k_gemm2<<<(N + 7) / 8, 256>>>(b1, W2, as2, ad2, N);
    k_max2<<<1024, 256>>>(as2, ad2);
    k_denominit2<<<nb, 256>>>(as2, ad2, N);
    k_edgedenom2<<<1024, 256>>>(as2, ad2);
    k_out2init<<<nb, 256>>>(as2, ad2, b2, out, N);
    k_agg2<<<1024, 256>>>(out);
}

// round 4
// speedup vs baseline: 1.3815x; 1.3105x over previous
#include <cuda_runtime.h>
#include <cstdint>

#define MAXN 100000
#define MAXE 1600000
#define HD 128
#define SLOPE 0.2f
#define SCAN_B 1024

// ---------------- scratch (device globals) ----------------
__device__ float g_xp1[(size_t)MAXN * HD];
__device__ float g_es[MAXN];
__device__ float g_ed[MAXN];
__device__ float g_xp2[MAXN];
__device__ int   g_cs[MAXE];        // compacted src
__device__ int   g_cd[MAXE];        // compacted dst
__device__ int   g_csr[MAXE];       // CSR: src per slot (dst-grouped)
__device__ int   g_deg[MAXN];
__device__ int   g_cur[MAXN];
__device__ int   g_scan[MAXN];
__device__ int   g_rowptr[MAXN + 1];
__device__ int   g_bsum[128];
__device__ int   g_boff[128];
__device__ int   g_cnt;

// ---------------- helpers ----------------
__device__ __forceinline__ float lrelu(float x) { return x > 0.f ? x : SLOPE * x; }

__device__ __forceinline__ uint32_t f2tf32(float f) {
    uint32_t r; asm("cvt.rna.tf32.f32 %0, %1;" : "=r"(r) : "f"(f)); return r;
}

__device__ __forceinline__ void mma_tf32(float* c, const uint32_t* a, const uint32_t* b) {
    asm volatile("mma.sync.aligned.m16n8k8.row.col.f32.tf32.tf32.f32 "
                 "{%0,%1,%2,%3}, {%4,%5,%6,%7}, {%8,%9}, {%0,%1,%2,%3};"
                 : "+f"(c[0]), "+f"(c[1]), "+f"(c[2]), "+f"(c[3])
                 : "r"(a[0]), "r"(a[1]), "r"(a[2]), "r"(a[3]), "r"(b[0]), "r"(b[1]));
}

// ---------------- edge preprocessing: compact + degree ----------------
__global__ void k_zero(int N) {
    int i = blockIdx.x * blockDim.x + threadIdx.x;
    if (i < N) g_deg[i] = 0;
    if (i == 0) g_cnt = 0;
}

__global__ void k_deg(const int* __restrict__ ei, const int* __restrict__ nt, int E) {
    int Er = (E + 31) & ~31;
    int lane = threadIdx.x & 31;
    int stride = gridDim.x * blockDim.x;
    for (int i = blockIdx.x * blockDim.x + threadIdx.x; i < Er; i += stride) {
        int s = 0, d = 0;
        bool act = false;
        if (i < E) {
            s = ei[i];
            d = ei[E + i];
            act = (__ldg(&nt[s]) == 0) && (__ldg(&nt[d]) == 0);
        }
        unsigned ball = __ballot_sync(0xffffffffu, act);
        if (ball) {
            int leader = __ffs(ball) - 1;
            int base = 0;
            if (lane == leader) base = atomicAdd(&g_cnt, __popc(ball));
            base = __shfl_sync(0xffffffffu, base, leader);
            if (act) {
                int off = __popc(ball & ((1u << lane) - 1u));
                g_cs[base + off] = s;
                g_cd[base + off] = d;
                atomicAdd(&g_deg[d], 1);
            }
        }
    }
}

// ---------------- exclusive scan of degrees -> rowptr / cursor ----------------
__global__ void __launch_bounds__(SCAN_B) k_scanA(int N) {
    __shared__ int sh[SCAN_B];
    int tid = threadIdx.x;
    int i = blockIdx.x * SCAN_B + tid;
    int v = (i < N) ? g_deg[i] : 0;
    sh[tid] = v;
    __syncthreads();
    for (int off = 1; off < SCAN_B; off <<= 1) {
        int t = (tid >= off) ? sh[tid - off] : 0;
        __syncthreads();
        sh[tid] += t;
        __syncthreads();
    }
    if (i < N) g_scan[i] = sh[tid];
    if (tid == SCAN_B - 1) g_bsum[blockIdx.x] = sh[tid];
}

__global__ void k_scanB(int nb) {
    if (threadIdx.x == 0 && blockIdx.x == 0) {
        int run = 0;
        for (int b = 0; b < nb; b++) { run += g_bsum[b]; g_boff[b] = run; }
    }
}

__global__ void k_scanC(int N) {
    int i = blockIdx.x * blockDim.x + threadIdx.x;
    if (i < N) {
        int b = i >> 10;
        int off = b ? g_boff[b - 1] : 0;
        int incl = off + g_scan[i];
        g_rowptr[i + 1] = incl;
        g_cur[i] = incl - g_deg[i];
        if (i == 0) g_rowptr[0] = 0;
    }
}

__global__ void k_scatter() {
    int cnt = g_cnt;
    int st = gridDim.x * blockDim.x;
    for (int i = blockIdx.x * blockDim.x + threadIdx.x; i < cnt; i += st) {
        int s = g_cs[i], d = g_cd[i];
        int pos = atomicAdd(&g_cur[d], 1);
        g_csr[pos] = s;
    }
}

// =======================================================================
// GEMM1: xp1 = emb[h] @ W1 via mma.sync tf32 (m16n8k8).
// CTA: 256 thr, 128x128 tile, K in 4 smem chunks of 32. Epilogue in four
// 32-row groups reusing staging smem; fused e_src/e_dst dots.
// =======================================================================
static constexpr int KPAD = 136;
static constexpr int OPAD = 132;
static constexpr int SM_TOT = 2 * 32 * KPAD * 4;   // 34816 B

__global__ void __launch_bounds__(256, 2)
k_gemm1_tc(const int* __restrict__ hidx, const float* __restrict__ emb,
           const float* __restrict__ W,
           const float* __restrict__ as1, const float* __restrict__ ad1, int N)
{
    extern __shared__ char smem[];
    uint32_t* xs = (uint32_t*)smem;                      // [32][KPAD]
    uint32_t* ws = (uint32_t*)(smem + 32 * KPAD * 4);    // [32][KPAD]
    float*    os = (float*)smem;                         // [32][OPAD] epilogue reuse

    int tid  = threadIdx.x;
    int lane = tid & 31;
    int wid  = tid >> 5;
    int g    = lane >> 2;
    int tg   = lane & 3;
    int m_base = (wid & 3) * 32;
    int n_base = (wid >> 2) * 64;
    int blk0 = blockIdx.x * 128;

    float acc[2][8][4];
#pragma unroll
    for (int mf = 0; mf < 2; mf++)
#pragma unroll
        for (int nf = 0; nf < 8; nf++)
#pragma unroll
            for (int q = 0; q < 4; q++) acc[mf][nf][q] = 0.f;

    int arow = tid >> 1;
    int ahalf = tid & 1;
    int grow = blk0 + arow;
    int hrow = (grow < N) ? __ldg(&hidx[grow]) : 0;
    const float4* aptr = (const float4*)&emb[(size_t)hrow * HD];

    int bkk = tid >> 3;
    int bseg = tid & 7;

    for (int kc = 0; kc < 4; kc++) {
#pragma unroll
        for (int q = 0; q < 4; q++) {
            float4 v = __ldg(&aptr[kc * 8 + ahalf * 4 + q]);
            int k = ahalf * 16 + q * 4;
            xs[(k + 0) * KPAD + arow] = f2tf32(v.x);
            xs[(k + 1) * KPAD + arow] = f2tf32(v.y);
            xs[(k + 2) * KPAD + arow] = f2tf32(v.z);
            xs[(k + 3) * KPAD + arow] = f2tf32(v.w);
        }
        {
            const float4* bptr = (const float4*)&W[(size_t)(kc * 32 + bkk) * HD + bseg * 16];
#pragma unroll
            for (int q = 0; q < 4; q++) {
                float4 v = __ldg(&bptr[q]);
                uint4 u = make_uint4(f2tf32(v.x), f2tf32(v.y), f2tf32(v.z), f2tf32(v.w));
                *(uint4*)&ws[bkk * KPAD + bseg * 16 + q * 4] = u;
            }
        }
        __syncthreads();

#pragma unroll
        for (int ks = 0; ks < 4; ks++) {
            int k0 = ks * 8;
            uint32_t af[2][4], bf[8][2];
#pragma unroll
            for (int mf = 0; mf < 2; mf++) {
                int m0 = m_base + mf * 16;
                af[mf][0] = xs[(k0 + tg) * KPAD + m0 + g];
                af[mf][1] = xs[(k0 + tg) * KPAD + m0 + g + 8];
                af[mf][2] = xs[(k0 + tg + 4) * KPAD + m0 + g];
                af[mf][3] = xs[(k0 + tg + 4) * KPAD + m0 + g + 8];
            }
#pragma unroll
            for (int nf = 0; nf < 8; nf++) {
                int n0 = n_base + nf * 8;
                bf[nf][0] = ws[(k0 + tg) * KPAD + n0 + g];
                bf[nf][1] = ws[(k0 + tg + 4) * KPAD + n0 + g];
            }
#pragma unroll
            for (int mf = 0; mf < 2; mf++)
#pragma unroll
                for (int nf = 0; nf < 8; nf++)
                    mma_tf32(acc[mf][nf], af[mf], bf[nf]);
        }
        __syncthreads();
    }

    // ---- epilogue: 4 row-groups of 32 through smem; fused es/ed dots ----
    float4 av = __ldg((const float4*)&as1[lane * 4]);
    float4 dv = __ldg((const float4*)&ad1[lane * 4]);
#pragma unroll
    for (int rg = 0; rg < 4; rg++) {
        if ((wid & 3) == rg) {
#pragma unroll
            for (int mf = 0; mf < 2; mf++) {
                int r0 = mf * 16 + g;
#pragma unroll
                for (int nf = 0; nf < 8; nf++) {
                    int c0 = n_base + nf * 8 + tg * 2;
                    os[r0 * OPAD + c0]           = acc[mf][nf][0];
                    os[r0 * OPAD + c0 + 1]       = acc[mf][nf][1];
                    os[(r0 + 8) * OPAD + c0]     = acc[mf][nf][2];
                    os[(r0 + 8) * OPAD + c0 + 1] = acc[mf][nf][3];
                }
            }
        }
        __syncthreads();
#pragma unroll
        for (int rr = 0; rr < 4; rr++) {
            int rl = wid * 4 + rr;
            int row = blk0 + rg * 32 + rl;
            float4 v = *(const float4*)&os[rl * OPAD + lane * 4];
            float ps = v.x * av.x + v.y * av.y + v.z * av.z + v.w * av.w;
            float pd = v.x * dv.x + v.y * dv.y + v.z * dv.z + v.w * dv.w;
#pragma unroll
            for (int off = 16; off; off >>= 1) {
                ps += __shfl_xor_sync(0xffffffffu, ps, off);
                pd += __shfl_xor_sync(0xffffffffu, pd, off);
            }
            if (row < N) {
                *(float4*)&g_xp1[(size_t)row * HD + lane * 4] = v;
                if (lane == 0) {
                    g_es[row] = ps;
                    g_ed[row] = pd;
                }
            }
        }
        __syncthreads();
    }
}

// =======================================================================
// Layer-1 fused node kernel (warp per node): segment softmax over CSR
// edges + self loop, aggregate xp1 in registers, then fused
// xp2 = relu(out1 + b1) . W2. Never materializes out1.
// =======================================================================
__global__ void __launch_bounds__(256) k_node1(
    const float* __restrict__ b1, const float* __restrict__ W2, int N)
{
    int lane = threadIdx.x & 31;
    int node = blockIdx.x * 8 + (threadIdx.x >> 5);
    if (node >= N) return;

    int r0 = __ldg(&g_rowptr[node]);
    int r1 = __ldg(&g_rowptr[node + 1]);
    float edv = g_ed[node];
    float selflg = lrelu(g_es[node] + edv);

    // pass 1: max logit
    float m = selflg;
    for (int e = r0 + lane; e < r1; e += 32)
        m = fmaxf(m, lrelu(__ldg(&g_es[g_csr[e]]) + edv));
#pragma unroll
    for (int off = 16; off; off >>= 1)
        m = fmaxf(m, __shfl_xor_sync(0xffffffffu, m, off));

    // pass 2: denominator
    float den = 0.f;
    for (int e = r0 + lane; e < r1; e += 32)
        den += __expf(lrelu(__ldg(&g_es[g_csr[e]]) + edv) - m);
#pragma unroll
    for (int off = 16; off; off >>= 1)
        den += __shfl_xor_sync(0xffffffffu, den, off);
    float sw = __expf(selflg - m);
    den += sw;
    float inv = __frcp_rn(den);

    // pass 3: aggregate (self + edges), 4 dims per lane
    float4 accv;
    {
        float a = sw * inv;
        float4 v = *(const float4*)&g_xp1[(size_t)node * HD + lane * 4];
        accv = make_float4(a * v.x, a * v.y, a * v.z, a * v.w);
    }
    for (int base = r0; base < r1; base += 32) {
        int e = base + lane;
        float wgt = 0.f; int src = 0;
        if (e < r1) {
            src = g_csr[e];
            wgt = __expf(lrelu(__ldg(&g_es[src]) + edv) - m) * inv;
        }
        int cnt = min(32, r1 - base);
        for (int j = 0; j < cnt; j++) {
            float wj = __shfl_sync(0xffffffffu, wgt, j);
            int   sj = __shfl_sync(0xffffffffu, src, j);
            float4 v = __ldg((const float4*)&g_xp1[(size_t)sj * HD] + lane);
            accv.x += wj * v.x; accv.y += wj * v.y;
            accv.z += wj * v.z; accv.w += wj * v.w;
        }
    }

    // fused layer-2 GEMV: xp2 = relu(out1 + b1) . W2
    float4 bb = __ldg((const float4*)&b1[lane * 4]);
    float4 ww = __ldg((const float4*)&W2[lane * 4]);
    float s = fmaxf(accv.x + bb.x, 0.f) * ww.x + fmaxf(accv.y + bb.y, 0.f) * ww.y +
              fmaxf(accv.z + bb.z, 0.f) * ww.z + fmaxf(accv.w + bb.w, 0.f) * ww.w;
#pragma unroll
    for (int off = 16; off; off >>= 1) s += __shfl_xor_sync(0xffffffffu, s, off);
    if (lane == 0) g_xp2[node] = s;
}

// =======================================================================
// Layer-2 fused node kernel (thread per node, OUT=1 scalar).
// =======================================================================
__global__ void k_node2(const float* __restrict__ as2, const float* __restrict__ ad2,
                        const float* __restrict__ b2, float* __restrict__ out, int N)
{
    int i = blockIdx.x * blockDim.x + threadIdx.x;
    if (i >= N) return;
    float a = __ldg(&as2[0]), b = __ldg(&ad2[0]);
    float xi = g_xp2[i];
    int r0 = g_rowptr[i], r1 = g_rowptr[i + 1];
    float xib = xi * b;
    float selflg = lrelu(xi * a + xib);
    float m = selflg;
    for (int e = r0; e < r1; e++)
        m = fmaxf(m, lrelu(__ldg(&g_xp2[g_csr[e]]) * a + xib));
    float sw = __expf(selflg - m);
    float den = sw, num = sw * xi;
    for (int e = r0; e < r1; e++) {
        float xs = __ldg(&g_xp2[g_csr[e]]);
        float w = __expf(lrelu(xs * a + xib) - m);
        den += w;
        num += w * xs;
    }
    out[i] = num / den + __ldg(&b2[0]);
}

// ---------------- launch ----------------
extern "C" void kernel_launch(void* const* d_in, const int* in_sizes, int n_in,
                              void* d_out, int out_size) {
    const int*   h    = (const int*)d_in[0];
    const int*   ei   = (const int*)d_in[1];
    const int*   nt   = (const int*)d_in[2];
    const float* emb  = (const float*)d_in[3];
    const float* W1   = (const float*)d_in[4];
    const float* as1  = (const float*)d_in[5];
    const float* ad1  = (const float*)d_in[6];
    const float* b1   = (const float*)d_in[7];
    const float* W2   = (const float*)d_in[8];
    const float* as2  = (const float*)d_in[9];
    const float* ad2  = (const float*)d_in[10];
    const float* b2   = (const float*)d_in[11];
    float* out = (float*)d_out;

    int N = in_sizes[0];
    int E = in_sizes[1] / 2;
    int nb = (N + 255) / 256;
    int nscan = (N + SCAN_B - 1) / SCAN_B;

    static bool attr_set = false;
    if (!attr_set) {
        cudaFuncSetAttribute(k_gemm1_tc, cudaFuncAttributeMaxDynamicSharedMemorySize, SM_TOT);
        attr_set = true;
    }

    // edge preprocessing -> CSR
    k_zero<<<nb, 256>>>(N);
    k_deg<<<1024, 256>>>(ei, nt, E);
    k_scanA<<<nscan, SCAN_B>>>(N);
    k_scanB<<<1, 32>>>(nscan);
    k_scanC<<<nb, 256>>>(N);
    k_scatter<<<1024, 256>>>();

    // layer 1 GEMM (overlaps nothing but is independent of CSR until node1)
    k_gemm1_tc<<<(N + 127) / 128, 256, SM_TOT>>>(h, emb, W1, as1, ad1, N);

    // fused layer-1 softmax+aggregate+GEMV
    k_node1<<<(N + 7) / 8, 256>>>(b1, W2, N);

    // fused layer-2
    k_node2<<<nb, 256>>>(as2, ad2, b2, out, N);
}

// round 5
// speedup vs baseline: 1.5753x; 1.1403x over previous
#include <cuda_runtime.h>
#include <cstdint>

#define MAXN 100000
#define MAXE 1600000
#define HD 128
#define SLOPE 0.2f
#define SCAN_B 1024

// ---------------- scratch (device globals) ----------------
__device__ float g_xp1[(size_t)MAXN * HD];
__device__ float g_es[MAXN];
__device__ float g_ed[MAXN];
__device__ float g_xp2[MAXN];
__device__ int   g_cs[MAXE];        // compacted src
__device__ int   g_cd[MAXE];        // compacted dst
__device__ int   g_csr[MAXE];       // CSR: src per slot (dst-grouped)
__device__ int   g_deg[MAXN];
__device__ int   g_cur[MAXN];
__device__ int   g_scan[MAXN];
__device__ int   g_rowptr[MAXN + 1];
__device__ int   g_bsum[128];
__device__ int   g_boff[128];
__device__ int   g_cnt;

// ---------------- helpers ----------------
__device__ __forceinline__ float lrelu(float x) { return x > 0.f ? x : SLOPE * x; }

__device__ __forceinline__ uint32_t f2tf32(float f) {
    uint32_t r; asm("cvt.rna.tf32.f32 %0, %1;" : "=r"(r) : "f"(f)); return r;
}

__device__ __forceinline__ void mma_tf32(float* c, const uint32_t* a, const uint32_t* b) {
    asm volatile("mma.sync.aligned.m16n8k8.row.col.f32.tf32.tf32.f32 "
                 "{%0,%1,%2,%3}, {%4,%5,%6,%7}, {%8,%9}, {%0,%1,%2,%3};"
                 : "+f"(c[0]), "+f"(c[1]), "+f"(c[2]), "+f"(c[3])
                 : "r"(a[0]), "r"(a[1]), "r"(a[2]), "r"(a[3]), "r"(b[0]), "r"(b[1]));
}

// ---------------- edge preprocessing: compact + degree ----------------
__global__ void k_zero(int N) {
    int i = blockIdx.x * blockDim.x + threadIdx.x;
    if (i < N) g_deg[i] = 0;
    if (i == 0) g_cnt = 0;
}

__global__ void k_deg(const int* __restrict__ ei, const int* __restrict__ nt, int E) {
    int Er = (E + 31) & ~31;
    int lane = threadIdx.x & 31;
    int stride = gridDim.x * blockDim.x;
    for (int i = blockIdx.x * blockDim.x + threadIdx.x; i < Er; i += stride) {
        int s = 0, d = 0;
        bool act = false;
        if (i < E) {
            s = ei[i];
            d = ei[E + i];
            act = (__ldg(&nt[s]) == 0) && (__ldg(&nt[d]) == 0);
        }
        unsigned ball = __ballot_sync(0xffffffffu, act);
        if (ball) {
            int leader = __ffs(ball) - 1;
            int base = 0;
            if (lane == leader) base = atomicAdd(&g_cnt, __popc(ball));
            base = __shfl_sync(0xffffffffu, base, leader);
            if (act) {
                int off = __popc(ball & ((1u << lane) - 1u));
                g_cs[base + off] = s;
                g_cd[base + off] = d;
                atomicAdd(&g_deg[d], 1);
            }
        }
    }
}

// ---------------- exclusive scan of degrees -> rowptr / cursor ----------------
__global__ void __launch_bounds__(SCAN_B) k_scanA(int N) {
    __shared__ int sh[SCAN_B];
    int tid = threadIdx.x;
    int i = blockIdx.x * SCAN_B + tid;
    int v = (i < N) ? g_deg[i] : 0;
    sh[tid] = v;
    __syncthreads();
    for (int off = 1; off < SCAN_B; off <<= 1) {
        int t = (tid >= off) ? sh[tid - off] : 0;
        __syncthreads();
        sh[tid] += t;
        __syncthreads();
    }
    if (i < N) g_scan[i] = sh[tid];
    if (tid == SCAN_B - 1) g_bsum[blockIdx.x] = sh[tid];
}

// parallel scan of block sums (nb <= 128), one 128-thread block
__global__ void __launch_bounds__(128) k_scanB(int nb) {
    __shared__ int sh[128];
    int tid = threadIdx.x;
    int v = (tid < nb) ? g_bsum[tid] : 0;
    sh[tid] = v;
    __syncthreads();
#pragma unroll
    for (int off = 1; off < 128; off <<= 1) {
        int t = (tid >= off) ? sh[tid - off] : 0;
        __syncthreads();
        sh[tid] += t;
        __syncthreads();
    }
    if (tid < nb) g_boff[tid] = sh[tid];
}

__global__ void k_scanC(int N) {
    int i = blockIdx.x * blockDim.x + threadIdx.x;
    if (i < N) {
        int b = i >> 10;
        int off = b ? g_boff[b - 1] : 0;
        int incl = off + g_scan[i];
        g_rowptr[i + 1] = incl;
        g_cur[i] = incl - g_deg[i];
        if (i == 0) g_rowptr[0] = 0;
    }
}

__global__ void k_scatter() {
    int cnt = g_cnt;
    int st = gridDim.x * blockDim.x;
    for (int i = blockIdx.x * blockDim.x + threadIdx.x; i < cnt; i += st) {
        int s = g_cs[i], d = g_cd[i];
        int pos = atomicAdd(&g_cur[d], 1);
        g_csr[pos] = s;
    }
}

// =======================================================================
// GEMM1: xp1 = emb[h] @ W1 via mma.sync tf32 (m16n8k8).
// CTA: 256 thr, 128x128 tile, K in 4 smem chunks of 32. Epilogue in four
// 32-row groups reusing staging smem; fused e_src/e_dst dots.
// =======================================================================
static constexpr int KPAD = 136;
static constexpr int OPAD = 132;
static constexpr int SM_TOT = 2 * 32 * KPAD * 4;   // 34816 B

__global__ void __launch_bounds__(256, 2)
k_gemm1_tc(const int* __restrict__ hidx, const float* __restrict__ emb,
           const float* __restrict__ W,
           const float* __restrict__ as1, const float* __restrict__ ad1, int N)
{
    extern __shared__ char smem[];
    uint32_t* xs = (uint32_t*)smem;                      // [32][KPAD]
    uint32_t* ws = (uint32_t*)(smem + 32 * KPAD * 4);    // [32][KPAD]
    float*    os = (float*)smem;                         // [32][OPAD] epilogue reuse

    int tid  = threadIdx.x;
    int lane = tid & 31;
    int wid  = tid >> 5;
    int g    = lane >> 2;
    int tg   = lane & 3;
    int m_base = (wid & 3) * 32;
    int n_base = (wid >> 2) * 64;
    int blk0 = blockIdx.x * 128;

    float acc[2][8][4];
#pragma unroll
    for (int mf = 0; mf < 2; mf++)
#pragma unroll
        for (int nf = 0; nf < 8; nf++)
#pragma unroll
            for (int q = 0; q < 4; q++) acc[mf][nf][q] = 0.f;

    int arow = tid >> 1;
    int ahalf = tid & 1;
    int grow = blk0 + arow;
    int hrow = (grow < N) ? __ldg(&hidx[grow]) : 0;
    const float4* aptr = (const float4*)&emb[(size_t)hrow * HD];

    int bkk = tid >> 3;
    int bseg = tid & 7;

    for (int kc = 0; kc < 4; kc++) {
#pragma unroll
        for (int q = 0; q < 4; q++) {
            float4 v = __ldg(&aptr[kc * 8 + ahalf * 4 + q]);
            int k = ahalf * 16 + q * 4;
            xs[(k + 0) * KPAD + arow] = f2tf32(v.x);
            xs[(k + 1) * KPAD + arow] = f2tf32(v.y);
            xs[(k + 2) * KPAD + arow] = f2tf32(v.z);
            xs[(k + 3) * KPAD + arow] = f2tf32(v.w);
        }
        {
            const float4* bptr = (const float4*)&W[(size_t)(kc * 32 + bkk) * HD + bseg * 16];
#pragma unroll
            for (int q = 0; q < 4; q++) {
                float4 v = __ldg(&bptr[q]);
                uint4 u = make_uint4(f2tf32(v.x), f2tf32(v.y), f2tf32(v.z), f2tf32(v.w));
                *(uint4*)&ws[bkk * KPAD + bseg * 16 + q * 4] = u;
            }
        }
        __syncthreads();

#pragma unroll
        for (int ks = 0; ks < 4; ks++) {
            int k0 = ks * 8;
            uint32_t af[2][4], bf[8][2];
#pragma unroll
            for (int mf = 0; mf < 2; mf++) {
                int m0 = m_base + mf * 16;
                af[mf][0] = xs[(k0 + tg) * KPAD + m0 + g];
                af[mf][1] = xs[(k0 + tg) * KPAD + m0 + g + 8];
                af[mf][2] = xs[(k0 + tg + 4) * KPAD + m0 + g];
                af[mf][3] = xs[(k0 + tg + 4) * KPAD + m0 + g + 8];
            }
#pragma unroll
            for (int nf = 0; nf < 8; nf++) {
                int n0 = n_base + nf * 8;
                bf[nf][0] = ws[(k0 + tg) * KPAD + n0 + g];
                bf[nf][1] = ws[(k0 + tg + 4) * KPAD + n0 + g];
            }
#pragma unroll
            for (int mf = 0; mf < 2; mf++)
#pragma unroll
                for (int nf = 0; nf < 8; nf++)
                    mma_tf32(acc[mf][nf], af[mf], bf[nf]);
        }
        __syncthreads();
    }

    // ---- epilogue: 4 row-groups of 32 through smem; fused es/ed dots ----
    float4 av = __ldg((const float4*)&as1[lane * 4]);
    float4 dv = __ldg((const float4*)&ad1[lane * 4]);
#pragma unroll
    for (int rg = 0; rg < 4; rg++) {
        if ((wid & 3) == rg) {
#pragma unroll
            for (int mf = 0; mf < 2; mf++) {
                int r0 = mf * 16 + g;
#pragma unroll
                for (int nf = 0; nf < 8; nf++) {
                    int c0 = n_base + nf * 8 + tg * 2;
                    os[r0 * OPAD + c0]           = acc[mf][nf][0];
                    os[r0 * OPAD + c0 + 1]       = acc[mf][nf][1];
                    os[(r0 + 8) * OPAD + c0]     = acc[mf][nf][2];
                    os[(r0 + 8) * OPAD + c0 + 1] = acc[mf][nf][3];
                }
            }
        }
        __syncthreads();
#pragma unroll
        for (int rr = 0; rr < 4; rr++) {
            int rl = wid * 4 + rr;
            int row = blk0 + rg * 32 + rl;
            float4 v = *(const float4*)&os[rl * OPAD + lane * 4];
            float ps = v.x * av.x + v.y * av.y + v.z * av.z + v.w * av.w;
            float pd = v.x * dv.x + v.y * dv.y + v.z * dv.z + v.w * dv.w;
#pragma unroll
            for (int off = 16; off; off >>= 1) {
                ps += __shfl_xor_sync(0xffffffffu, ps, off);
                pd += __shfl_xor_sync(0xffffffffu, pd, off);
            }
            if (row < N) {
                *(float4*)&g_xp1[(size_t)row * HD + lane * 4] = v;
                if (lane == 0) {
                    g_es[row] = ps;
                    g_ed[row] = pd;
                }
            }
        }
        __syncthreads();
    }
}

// =======================================================================
// Layer-1 fused node kernel (warp per node): segment softmax over CSR
// edges + self loop, aggregate xp1 in registers, then fused
// xp2 = relu(out1 + b1) . W2. Never materializes out1.
// =======================================================================
__global__ void __launch_bounds__(256) k_node1(
    const float* __restrict__ b1, const float* __restrict__ W2, int N)
{
    int lane = threadIdx.x & 31;
    int node = blockIdx.x * 8 + (threadIdx.x >> 5);
    if (node >= N) return;

    int r0 = __ldg(&g_rowptr[node]);
    int r1 = __ldg(&g_rowptr[node + 1]);
    float edv = g_ed[node];
    float selflg = lrelu(g_es[node] + edv);

    // pass 1: max logit
    float m = selflg;
    for (int e = r0 + lane; e < r1; e += 32)
        m = fmaxf(m, lrelu(__ldg(&g_es[g_csr[e]]) + edv));
#pragma unroll
    for (int off = 16; off; off >>= 1)
        m = fmaxf(m, __shfl_xor_sync(0xffffffffu, m, off));

    // pass 2: denominator
    float den = 0.f;
    for (int e = r0 + lane; e < r1; e += 32)
        den += __expf(lrelu(__ldg(&g_es[g_csr[e]]) + edv) - m);
#pragma unroll
    for (int off = 16; off; off >>= 1)
        den += __shfl_xor_sync(0xffffffffu, den, off);
    float sw = __expf(selflg - m);
    den += sw;
    float inv = __frcp_rn(den);

    // pass 3: aggregate (self + edges), 4 dims per lane
    float4 accv;
    {
        float a = sw * inv;
        float4 v = *(const float4*)&g_xp1[(size_t)node * HD + lane * 4];
        accv = make_float4(a * v.x, a * v.y, a * v.z, a * v.w);
    }
    for (int base = r0; base < r1; base += 32) {
        int e = base + lane;
        float wgt = 0.f; int src = 0;
        if (e < r1) {
            src = g_csr[e];
            wgt = __expf(lrelu(__ldg(&g_es[src]) + edv) - m) * inv;
        }
        int cnt = min(32, r1 - base);
        for (int j = 0; j < cnt; j++) {
            float wj = __shfl_sync(0xffffffffu, wgt, j);
            int   sj = __shfl_sync(0xffffffffu, src, j);
            float4 v = __ldg((const float4*)&g_xp1[(size_t)sj * HD] + lane);
            accv.x += wj * v.x; accv.y += wj * v.y;
            accv.z += wj * v.z; accv.w += wj * v.w;
        }
    }

    // fused layer-2 GEMV: xp2 = relu(out1 + b1) . W2
    float4 bb = __ldg((const float4*)&b1[lane * 4]);
    float4 ww = __ldg((const float4*)&W2[lane * 4]);
    float s = fmaxf(accv.x + bb.x, 0.f) * ww.x + fmaxf(accv.y + bb.y, 0.f) * ww.y +
              fmaxf(accv.z + bb.z, 0.f) * ww.z + fmaxf(accv.w + bb.w, 0.f) * ww.w;
#pragma unroll
    for (int off = 16; off; off >>= 1) s += __shfl_xor_sync(0xffffffffu, s, off);
    if (lane == 0) g_xp2[node] = s;
}

// =======================================================================
// Layer-2 fused node kernel (thread per node, OUT=1 scalar).
// =======================================================================
__global__ void k_node2(const float* __restrict__ as2, const float* __restrict__ ad2,
                        const float* __restrict__ b2, float* __restrict__ out, int N)
{
    int i = blockIdx.x * blockDim.x + threadIdx.x;
    if (i >= N) return;
    float a = __ldg(&as2[0]), b = __ldg(&ad2[0]);
    float xi = g_xp2[i];
    int r0 = g_rowptr[i], r1 = g_rowptr[i + 1];
    float xib = xi * b;
    float selflg = lrelu(xi * a + xib);
    float m = selflg;
    for (int e = r0; e < r1; e++)
        m = fmaxf(m, lrelu(__ldg(&g_xp2[g_csr[e]]) * a + xib));
    float sw = __expf(selflg - m);
    float den = sw, num = sw * xi;
    for (int e = r0; e < r1; e++) {
        float xs = __ldg(&g_xp2[g_csr[e]]);
        float w = __expf(lrelu(xs * a + xib) - m);
        den += w;
        num += w * xs;
    }
    out[i] = num / den + __ldg(&b2[0]);
}

// ---------------- launch ----------------
extern "C" void kernel_launch(void* const* d_in, const int* in_sizes, int n_in,
                              void* d_out, int out_size) {
    const int*   h    = (const int*)d_in[0];
    const int*   ei   = (const int*)d_in[1];
    const int*   nt   = (const int*)d_in[2];
    const float* emb  = (const float*)d_in[3];
    const float* W1   = (const float*)d_in[4];
    const float* as1  = (const float*)d_in[5];
    const float* ad1  = (const float*)d_in[6];
    const float* b1   = (const float*)d_in[7];
    const float* W2   = (const float*)d_in[8];
    const float* as2  = (const float*)d_in[9];
    const float* ad2  = (const float*)d_in[10];
    const float* b2   = (const float*)d_in[11];
    float* out = (float*)d_out;

    int N = in_sizes[0];
    int E = in_sizes[1] / 2;
    int nb = (N + 255) / 256;
    int nscan = (N + SCAN_B - 1) / SCAN_B;

    // one-time setup (first call is the non-captured correctness run)
    static cudaStream_t s2 = nullptr;
    static cudaEvent_t evFork = nullptr, evJoin = nullptr;
    if (!s2) {
        cudaFuncSetAttribute(k_gemm1_tc, cudaFuncAttributeMaxDynamicSharedMemorySize, SM_TOT);
        cudaStreamCreateWithFlags(&s2, cudaStreamNonBlocking);
        cudaEventCreateWithFlags(&evFork, cudaEventDisableTiming);
        cudaEventCreateWithFlags(&evJoin, cudaEventDisableTiming);
    }

    // fork: GEMM1 runs on s2 concurrently with the CSR build
    cudaEventRecord(evFork, 0);
    cudaStreamWaitEvent(s2, evFork, 0);
    k_gemm1_tc<<<(N + 127) / 128, 256, SM_TOT, s2>>>(h, emb, W1, as1, ad1, N);
    cudaEventRecord(evJoin, s2);

    // edge preprocessing -> CSR (main stream)
    k_zero<<<nb, 256>>>(N);
    k_deg<<<1024, 256>>>(ei, nt, E);
    k_scanA<<<nscan, SCAN_B>>>(N);
    k_scanB<<<1, 128>>>(nscan);
    k_scanC<<<nb, 256>>>(N);
    k_scatter<<<1024, 256>>>();

    // join: node1 needs both CSR and GEMM1 results
    cudaStreamWaitEvent(0, evJoin, 0);

    // fused layer-1 softmax+aggregate+GEMV
    k_node1<<<(N + 7) / 8, 256>>>(b1, W2, N);

    // fused layer-2
    k_node2<<<nb, 256>>>(as2, ad2, b2, out, N);
}